// round 1
// baseline (speedup 1.0000x reference)
#include <cuda_runtime.h>
#include <math_constants.h>

#define BB 4
#define TT 2048
#define CC 768
#define HH 64

// scratch for Q, K, V: [B, T, H] each
__device__ float g_q[BB * TT * HH];
__device__ float g_k[BB * TT * HH];
__device__ float g_v[BB * TT * HH];

// ---------------------------------------------------------------------------
// Kernel 1: QKV projection. One block per (b, t) row. 64 threads = one per h.
// x row (768 floats) staged in shared; W reads coalesced across h.
// ---------------------------------------------------------------------------
__global__ __launch_bounds__(64) void qkv_kernel(
    const float* __restrict__ x,
    const float* __restrict__ Wq,
    const float* __restrict__ Wk,
    const float* __restrict__ Wv)
{
    int bt = blockIdx.x;          // 0..B*T-1
    int h  = threadIdx.x;         // 0..63

    __shared__ float xs[CC];
    const float* xr = x + (size_t)bt * CC;
    for (int c = h; c < CC; c += 64) xs[c] = xr[c];
    __syncthreads();

    float q = 0.f, k = 0.f, v = 0.f;
#pragma unroll 4
    for (int c = 0; c < CC; ++c) {
        float xv = xs[c];
        q = fmaf(xv, Wq[c * HH + h], q);
        k = fmaf(xv, Wk[c * HH + h], k);
        v = fmaf(xv, Wv[c * HH + h], v);
    }
    int o = bt * HH + h;
    g_q[o] = q;
    g_k[o] = k;
    g_v[o] = v;
}

// ---------------------------------------------------------------------------
// Kernel 2: causal attention. One block per (b, t) query row, 128 threads.
// Two-pass softmax with scores in shared memory (<= 8 KB), then PV with
// j-dimension split across two half-blocks.
// ---------------------------------------------------------------------------
__global__ __launch_bounds__(128) void attn_kernel(float* __restrict__ out)
{
    int bt  = blockIdx.x;
    int b   = bt / TT;
    int t   = bt % TT;
    int tid = threadIdx.x;
    int nk  = t + 1;              // causal: keys 0..t

    __shared__ float qs[HH];
    __shared__ float s[TT];       // scores / probabilities
    __shared__ float wred[4];
    __shared__ float acc2[128];

    if (tid < HH) qs[tid] = g_q[bt * HH + tid];
    __syncthreads();

    const float scale = 0.125f;   // 1/sqrt(64)

    // Pass 1: scores + running max
    float lmax = -CUDART_INF_F;
    const float* kbase = g_k + (size_t)b * TT * HH;
    for (int j = tid; j < nk; j += 128) {
        const float4* kr = (const float4*)(kbase + (size_t)j * HH);
        float acc = 0.f;
#pragma unroll
        for (int hq = 0; hq < HH / 4; ++hq) {
            float4 kv = kr[hq];
            acc = fmaf(qs[hq * 4 + 0], kv.x, acc);
            acc = fmaf(qs[hq * 4 + 1], kv.y, acc);
            acc = fmaf(qs[hq * 4 + 2], kv.z, acc);
            acc = fmaf(qs[hq * 4 + 3], kv.w, acc);
        }
        acc *= scale;
        s[j] = acc;
        lmax = fmaxf(lmax, acc);
    }
    // block max reduce
#pragma unroll
    for (int o = 16; o; o >>= 1)
        lmax = fmaxf(lmax, __shfl_xor_sync(0xffffffff, lmax, o));
    if ((tid & 31) == 0) wred[tid >> 5] = lmax;
    __syncthreads();
    float bmax = fmaxf(fmaxf(wred[0], wred[1]), fmaxf(wred[2], wred[3]));
    __syncthreads();

    // Pass 2: exp + sum
    float lsum = 0.f;
    for (int j = tid; j < nk; j += 128) {
        float e = __expf(s[j] - bmax);
        s[j] = e;
        lsum += e;
    }
#pragma unroll
    for (int o = 16; o; o >>= 1)
        lsum += __shfl_xor_sync(0xffffffff, lsum, o);
    if ((tid & 31) == 0) wred[tid >> 5] = lsum;
    __syncthreads();
    float inv = 1.f / (wred[0] + wred[1] + wred[2] + wred[3]);
    __syncthreads();

    // PV: thread tid handles h = tid%64, j parity = tid/64
    int h    = tid & 63;
    int half = tid >> 6;
    const float* vbase = g_v + (size_t)b * TT * HH + h;
    float acc = 0.f;
    for (int j = half; j < nk; j += 2)
        acc = fmaf(s[j], vbase[(size_t)j * HH], acc);
    acc2[tid] = acc;
    __syncthreads();
    if (tid < HH)
        out[bt * HH + tid] = (acc2[tid] + acc2[tid + 64]) * inv;
}

extern "C" void kernel_launch(void* const* d_in, const int* in_sizes, int n_in,
                              void* d_out, int out_size)
{
    const float* x  = (const float*)d_in[0];
    const float* Wq = (const float*)d_in[1];
    const float* Wk = (const float*)d_in[2];
    const float* Wv = (const float*)d_in[3];
    float* out = (float*)d_out;

    qkv_kernel<<<BB * TT, 64>>>(x, Wq, Wk, Wv);
    attn_kernel<<<BB * TT, 128>>>(out);
}

// round 3
// speedup vs baseline: 3.6500x; 3.6500x over previous
#include <cuda_runtime.h>
#include <math_constants.h>

#define BB 4
#define TT 2048
#define CC 768
#define HH 64
#define BQ 32
#define BK 64

__device__ float g_q[BB * TT * HH];
__device__ float g_k[BB * TT * HH];
__device__ float g_v[BB * TT * HH];

// ---------------------------------------------------------------------------
// QKV projection: tiled GEMM. Block = 64 rows x 64 cols of one of Wq/Wk/Wv.
// 256 threads, 4x4 register tile per thread. grid = 128*3 = 384 blocks.
// ---------------------------------------------------------------------------
__global__ __launch_bounds__(256) void qkv_kernel(
    const float* __restrict__ x,
    const float* __restrict__ Wq,
    const float* __restrict__ Wk,
    const float* __restrict__ Wv)
{
    int blk = blockIdx.x;
    int sel = blk % 3;
    int mt  = blk / 3;              // 0..127
    const float* W = (sel == 0) ? Wq : (sel == 1) ? Wk : Wv;
    float* G       = (sel == 0) ? g_q : (sel == 1) ? g_k : g_v;

    int tid = threadIdx.x;
    int tx  = tid & 15;             // col group
    int ty  = tid >> 4;             // row group

    __shared__ float Xs[32][64];    // [c][m]
    __shared__ float Ws[32][64];    // [c][n]

    float acc[4][4];
#pragma unroll
    for (int i = 0; i < 4; ++i)
#pragma unroll
        for (int j = 0; j < 4; ++j) acc[i][j] = 0.f;

    int m_ld  = tid >> 2;               // 0..63
    int cb_ld = (tid & 3) << 3;         // 0,8,16,24
    int c_wl  = tid >> 3;               // 0..31
    int nb_wl = (tid & 7) << 3;         // 0..56

    for (int ct = 0; ct < CC; ct += 32) {
        // X tile (transposed into smem)
        const float4* xr = (const float4*)(x + (size_t)(mt * 64 + m_ld) * CC + ct + cb_ld);
        float4 u0 = xr[0];
        float4 u1 = xr[1];
        Xs[cb_ld + 0][m_ld] = u0.x; Xs[cb_ld + 1][m_ld] = u0.y;
        Xs[cb_ld + 2][m_ld] = u0.z; Xs[cb_ld + 3][m_ld] = u0.w;
        Xs[cb_ld + 4][m_ld] = u1.x; Xs[cb_ld + 5][m_ld] = u1.y;
        Xs[cb_ld + 6][m_ld] = u1.z; Xs[cb_ld + 7][m_ld] = u1.w;
        // W tile (natural layout)
        const float4* wr = (const float4*)(W + (size_t)(ct + c_wl) * HH + nb_wl);
        float4 w0 = wr[0];
        float4 w1 = wr[1];
        *(float4*)&Ws[c_wl][nb_wl]     = w0;
        *(float4*)&Ws[c_wl][nb_wl + 4] = w1;
        __syncthreads();

#pragma unroll 8
        for (int c = 0; c < 32; ++c) {
            float4 a = *(const float4*)&Xs[c][ty << 2];
            float4 b = *(const float4*)&Ws[c][tx << 2];
            acc[0][0] = fmaf(a.x, b.x, acc[0][0]); acc[0][1] = fmaf(a.x, b.y, acc[0][1]);
            acc[0][2] = fmaf(a.x, b.z, acc[0][2]); acc[0][3] = fmaf(a.x, b.w, acc[0][3]);
            acc[1][0] = fmaf(a.y, b.x, acc[1][0]); acc[1][1] = fmaf(a.y, b.y, acc[1][1]);
            acc[1][2] = fmaf(a.y, b.z, acc[1][2]); acc[1][3] = fmaf(a.y, b.w, acc[1][3]);
            acc[2][0] = fmaf(a.z, b.x, acc[2][0]); acc[2][1] = fmaf(a.z, b.y, acc[2][1]);
            acc[2][2] = fmaf(a.z, b.z, acc[2][2]); acc[2][3] = fmaf(a.z, b.w, acc[2][3]);
            acc[3][0] = fmaf(a.w, b.x, acc[3][0]); acc[3][1] = fmaf(a.w, b.y, acc[3][1]);
            acc[3][2] = fmaf(a.w, b.z, acc[3][2]); acc[3][3] = fmaf(a.w, b.w, acc[3][3]);
        }
        __syncthreads();
    }

#pragma unroll
    for (int i = 0; i < 4; ++i) {
        float4 r = make_float4(acc[i][0], acc[i][1], acc[i][2], acc[i][3]);
        *(float4*)&G[(size_t)(mt * 64 + (ty << 2) + i) * HH + (tx << 2)] = r;
    }
}

// ---------------------------------------------------------------------------
// Flash-attention (fp32). Block = 32 queries, loops over 64-key tiles.
// 128 threads; S and O microkernels use 4x4 register tiles (8x16 thread grid).
// LPT: blocks with the longest causal prefix launch first.
// ---------------------------------------------------------------------------
__global__ __launch_bounds__(128) void attn_kernel(float* __restrict__ out)
{
    int blk = blockIdx.x;                 // 0..255
    int b   = blk & 3;
    int qt  = 63 - (blk >> 2);            // largest first
    int tid = threadIdx.x;
    int tx  = tid & 15;                   // key / h col group
    int ty  = tid >> 4;                   // query row group (0..7)

    __shared__ float Qs[64][32];          // [h][q]
    __shared__ float Ks[64][64];          // [h][k]
    __shared__ float Vs[64][64];          // [k][h]
    __shared__ float Ps[32][64];          // [q][k]

    // load Q tile (transposed)
    {
        int q  = tid >> 2;                // 0..31
        int hb = (tid & 3) << 4;          // 0,16,32,48
        const float4* qr = (const float4*)(g_q + (size_t)(b * TT + qt * BQ + q) * HH + hb);
#pragma unroll
        for (int i = 0; i < 4; ++i) {
            float4 v = qr[i];
            Qs[hb + 4 * i + 0][q] = v.x;
            Qs[hb + 4 * i + 1][q] = v.y;
            Qs[hb + 4 * i + 2][q] = v.z;
            Qs[hb + 4 * i + 3][q] = v.w;
        }
    }

    float o[4][4];
    float m[4], l[4];
#pragma unroll
    for (int i = 0; i < 4; ++i) {
        m[i] = -CUDART_INF_F; l[i] = 0.f;
#pragma unroll
        for (int j = 0; j < 4; ++j) o[i][j] = 0.f;
    }

    int nkt = (qt * BQ + BQ + 63) >> 6;   // key tiles needed
    int k_ld  = tid >> 2;                 // 0..31 (two keys per thread: +0, +32)
    int hb_ld = (tid & 3) << 4;

    for (int kt = 0; kt < nkt; ++kt) {
        __syncthreads();
        // load K tile (transposed): each thread loads 2 keys x 16 h values
        {
#pragma unroll
            for (int kk = 0; kk < 2; ++kk) {
                int kx = k_ld + kk * 32;
                const float4* kr = (const float4*)(g_k + (size_t)(b * TT + kt * BK + kx) * HH + hb_ld);
#pragma unroll
                for (int i = 0; i < 4; ++i) {
                    float4 v = kr[i];
                    Ks[hb_ld + 4 * i + 0][kx] = v.x;
                    Ks[hb_ld + 4 * i + 1][kx] = v.y;
                    Ks[hb_ld + 4 * i + 2][kx] = v.z;
                    Ks[hb_ld + 4 * i + 3][kx] = v.w;
                }
            }
            // V tile (natural layout): 1024 float4 / 128 threads
            const float4* vsrc = (const float4*)(g_v + (size_t)(b * TT + kt * BK) * HH);
            float4* vdst = (float4*)&Vs[0][0];
#pragma unroll
            for (int r = 0; r < 8; ++r)
                vdst[tid + 128 * r] = vsrc[tid + 128 * r];
        }
        __syncthreads();

        // S = Q K^T
        float s[4][4];
#pragma unroll
        for (int i = 0; i < 4; ++i)
#pragma unroll
            for (int j = 0; j < 4; ++j) s[i][j] = 0.f;

#pragma unroll 8
        for (int h = 0; h < HH; ++h) {
            float4 a = *(const float4*)&Qs[h][ty << 2];
            float4 bk = *(const float4*)&Ks[h][tx << 2];
            s[0][0] = fmaf(a.x, bk.x, s[0][0]); s[0][1] = fmaf(a.x, bk.y, s[0][1]);
            s[0][2] = fmaf(a.x, bk.z, s[0][2]); s[0][3] = fmaf(a.x, bk.w, s[0][3]);
            s[1][0] = fmaf(a.y, bk.x, s[1][0]); s[1][1] = fmaf(a.y, bk.y, s[1][1]);
            s[1][2] = fmaf(a.y, bk.z, s[1][2]); s[1][3] = fmaf(a.y, bk.w, s[1][3]);
            s[2][0] = fmaf(a.z, bk.x, s[2][0]); s[2][1] = fmaf(a.z, bk.y, s[2][1]);
            s[2][2] = fmaf(a.z, bk.z, s[2][2]); s[2][3] = fmaf(a.z, bk.w, s[2][3]);
            s[3][0] = fmaf(a.w, bk.x, s[3][0]); s[3][1] = fmaf(a.w, bk.y, s[3][1]);
            s[3][2] = fmaf(a.w, bk.z, s[3][2]); s[3][3] = fmaf(a.w, bk.w, s[3][3]);
        }

        const float scale = 0.125f;
        bool lastkt = (kt == nkt - 1);
#pragma unroll
        for (int i = 0; i < 4; ++i) {
            int qg = qt * BQ + (ty << 2) + i;
#pragma unroll
            for (int j = 0; j < 4; ++j) {
                s[i][j] *= scale;
                if (lastkt) {
                    int kg = kt * BK + (tx << 2) + j;
                    if (kg > qg) s[i][j] = -CUDART_INF_F;
                }
            }
        }

        // online softmax per row
#pragma unroll
        for (int i = 0; i < 4; ++i) {
            float rm = fmaxf(fmaxf(s[i][0], s[i][1]), fmaxf(s[i][2], s[i][3]));
#pragma unroll
            for (int off = 8; off; off >>= 1)
                rm = fmaxf(rm, __shfl_xor_sync(0xffffffff, rm, off));
            float mn = fmaxf(m[i], rm);
            float corr = __expf(m[i] - mn);
            m[i] = mn;
            float rs = 0.f;
#pragma unroll
            for (int j = 0; j < 4; ++j) {
                float p = __expf(s[i][j] - mn);
                s[i][j] = p;
                rs += p;
            }
#pragma unroll
            for (int off = 8; off; off >>= 1)
                rs += __shfl_xor_sync(0xffffffff, rs, off);
            l[i] = l[i] * corr + rs;
#pragma unroll
            for (int j = 0; j < 4; ++j) o[i][j] *= corr;
            *(float4*)&Ps[(ty << 2) + i][tx << 2] =
                make_float4(s[i][0], s[i][1], s[i][2], s[i][3]);
        }
        __syncthreads();

        // O += P V
#pragma unroll 4
        for (int k4 = 0; k4 < 16; ++k4) {
            float4 p0 = *(const float4*)&Ps[(ty << 2) + 0][k4 << 2];
            float4 p1 = *(const float4*)&Ps[(ty << 2) + 1][k4 << 2];
            float4 p2 = *(const float4*)&Ps[(ty << 2) + 2][k4 << 2];
            float4 p3 = *(const float4*)&Ps[(ty << 2) + 3][k4 << 2];
#pragma unroll
            for (int r = 0; r < 4; ++r) {
                float4 v = *(const float4*)&Vs[(k4 << 2) + r][tx << 2];
                float pa = (r == 0) ? p0.x : (r == 1) ? p0.y : (r == 2) ? p0.z : p0.w;
                float pb = (r == 0) ? p1.x : (r == 1) ? p1.y : (r == 2) ? p1.z : p1.w;
                float pc = (r == 0) ? p2.x : (r == 1) ? p2.y : (r == 2) ? p2.z : p2.w;
                float pd = (r == 0) ? p3.x : (r == 1) ? p3.y : (r == 2) ? p3.z : p3.w;
                o[0][0] = fmaf(pa, v.x, o[0][0]); o[0][1] = fmaf(pa, v.y, o[0][1]);
                o[0][2] = fmaf(pa, v.z, o[0][2]); o[0][3] = fmaf(pa, v.w, o[0][3]);
                o[1][0] = fmaf(pb, v.x, o[1][0]); o[1][1] = fmaf(pb, v.y, o[1][1]);
                o[1][2] = fmaf(pb, v.z, o[1][2]); o[1][3] = fmaf(pb, v.w, o[1][3]);
                o[2][0] = fmaf(pc, v.x, o[2][0]); o[2][1] = fmaf(pc, v.y, o[2][1]);
                o[2][2] = fmaf(pc, v.z, o[2][2]); o[2][3] = fmaf(pc, v.w, o[2][3]);
                o[3][0] = fmaf(pd, v.x, o[3][0]); o[3][1] = fmaf(pd, v.y, o[3][1]);
                o[3][2] = fmaf(pd, v.z, o[3][2]); o[3][3] = fmaf(pd, v.w, o[3][3]);
            }
        }
    }

#pragma unroll
    for (int i = 0; i < 4; ++i) {
        float inv = 1.f / l[i];
        float4 r = make_float4(o[i][0] * inv, o[i][1] * inv, o[i][2] * inv, o[i][3] * inv);
        *(float4*)&out[(size_t)(b * TT + qt * BQ + (ty << 2) + i) * HH + (tx << 2)] = r;
    }
}

extern "C" void kernel_launch(void* const* d_in, const int* in_sizes, int n_in,
                              void* d_out, int out_size)
{
    const float* x  = (const float*)d_in[0];
    const float* Wq = (const float*)d_in[1];
    const float* Wk = (const float*)d_in[2];
    const float* Wv = (const float*)d_in[3];
    float* out = (float*)d_out;

    qkv_kernel<<<128 * 3, 256>>>(x, Wq, Wk, Wv);
    attn_kernel<<<64 * 4, 128>>>(out);
}

// round 4
// speedup vs baseline: 4.7426x; 1.2993x over previous
#include <cuda_runtime.h>
#include <math_constants.h>

#define BB 4
#define TT 2048
#define CC 768
#define HH 64
#define BQ 32
#define BK 64
#define NS 4   // kv splits

__device__ float g_q[BB * TT * HH];
__device__ float g_k[BB * TT * HH];
__device__ float g_v[BB * TT * HH];
// partial results per split: unnormalized O, row max m, row sum l
__device__ float g_po[NS * BB * TT * HH];
__device__ float g_pm[NS * BB * TT];
__device__ float g_pl[NS * BB * TT];

typedef unsigned long long ull;

__device__ __forceinline__ void ffma2(ull& d, ull a, ull b) {
    asm("fma.rn.f32x2 %0, %1, %2, %0;" : "+l"(d) : "l"(a), "l"(b));
}
__device__ __forceinline__ ull mul2(ull a, ull b) {
    ull r; asm("mul.rn.f32x2 %0, %1, %2;" : "=l"(r) : "l"(a), "l"(b)); return r;
}
__device__ __forceinline__ ull dup2(float x) {
    ull r; asm("mov.b64 %0, {%1, %1};" : "=l"(r) : "f"(x)); return r;
}
__device__ __forceinline__ float2 up2(ull v) {
    float2 r; asm("mov.b64 {%0, %1}, %2;" : "=f"(r.x), "=f"(r.y) : "l"(v)); return r;
}

// ---------------------------------------------------------------------------
// QKV projection, FFMA2 microkernel. 64x64 tile, 256 threads, 4x4 per thread.
// ---------------------------------------------------------------------------
__global__ __launch_bounds__(256) void qkv_kernel(
    const float* __restrict__ x,
    const float* __restrict__ Wq,
    const float* __restrict__ Wk,
    const float* __restrict__ Wv)
{
    int blk = blockIdx.x;
    int sel = blk % 3;
    int mt  = blk / 3;
    const float* W = (sel == 0) ? Wq : (sel == 1) ? Wk : Wv;
    float* G       = (sel == 0) ? g_q : (sel == 1) ? g_k : g_v;

    int tid = threadIdx.x;
    int tx  = tid & 15;
    int ty  = tid >> 4;

    __shared__ float Xs[32][64];
    __shared__ float Ws[32][64];

    ull acc2[4][2];
#pragma unroll
    for (int i = 0; i < 4; ++i) { acc2[i][0] = 0ULL; acc2[i][1] = 0ULL; }

    int m_ld  = tid >> 2;
    int cb_ld = (tid & 3) << 3;
    int c_wl  = tid >> 3;
    int nb_wl = (tid & 7) << 3;

    for (int ct = 0; ct < CC; ct += 32) {
        const float4* xr = (const float4*)(x + (size_t)(mt * 64 + m_ld) * CC + ct + cb_ld);
        float4 u0 = xr[0];
        float4 u1 = xr[1];
        Xs[cb_ld + 0][m_ld] = u0.x; Xs[cb_ld + 1][m_ld] = u0.y;
        Xs[cb_ld + 2][m_ld] = u0.z; Xs[cb_ld + 3][m_ld] = u0.w;
        Xs[cb_ld + 4][m_ld] = u1.x; Xs[cb_ld + 5][m_ld] = u1.y;
        Xs[cb_ld + 6][m_ld] = u1.z; Xs[cb_ld + 7][m_ld] = u1.w;
        const float4* wr = (const float4*)(W + (size_t)(ct + c_wl) * HH + nb_wl);
        float4 w0 = wr[0];
        float4 w1 = wr[1];
        *(float4*)&Ws[c_wl][nb_wl]     = w0;
        *(float4*)&Ws[c_wl][nb_wl + 4] = w1;
        __syncthreads();

#pragma unroll 8
        for (int c = 0; c < 32; ++c) {
            float4 a = *(const float4*)&Xs[c][ty << 2];
            ulonglong2 bp = *(const ulonglong2*)&Ws[c][tx << 2];
            ull a0 = dup2(a.x), a1 = dup2(a.y), a2 = dup2(a.z), a3 = dup2(a.w);
            ffma2(acc2[0][0], a0, bp.x); ffma2(acc2[0][1], a0, bp.y);
            ffma2(acc2[1][0], a1, bp.x); ffma2(acc2[1][1], a1, bp.y);
            ffma2(acc2[2][0], a2, bp.x); ffma2(acc2[2][1], a2, bp.y);
            ffma2(acc2[3][0], a3, bp.x); ffma2(acc2[3][1], a3, bp.y);
        }
        __syncthreads();
    }

#pragma unroll
    for (int i = 0; i < 4; ++i) {
        float2 lo = up2(acc2[i][0]);
        float2 hi = up2(acc2[i][1]);
        float4 r = make_float4(lo.x, lo.y, hi.x, hi.y);
        *(float4*)&G[(size_t)(mt * 64 + (ty << 2) + i) * HH + (tx << 2)] = r;
    }
}

// ---------------------------------------------------------------------------
// Flash-attention partial, kv-split. Block = (qt, b, s). 128 threads.
// Writes unnormalized O + (m, l) per row to scratch; combine kernel merges.
// ---------------------------------------------------------------------------
__global__ __launch_bounds__(128) void attn_split_kernel()
{
    int blk = blockIdx.x;                 // 0..1023, LPT order
    int s   = blk & 3;
    int b   = (blk >> 2) & 3;
    int qt  = 63 - (blk >> 4);
    int tid = threadIdx.x;
    int tx  = tid & 15;
    int ty  = tid >> 4;

    int nkt = (qt + 2) >> 1;              // total 64-key tiles for this q-tile
    int t0  = (s * nkt) >> 2;
    int t1  = ((s + 1) * nkt) >> 2;

    float* po = g_po + ((size_t)(s * BB + b) * TT + qt * BQ) * HH;
    float* pm = g_pm + (size_t)(s * BB + b) * TT + qt * BQ;
    float* pl = g_pl + (size_t)(s * BB + b) * TT + qt * BQ;

    if (t0 == t1) {
        // empty split: zero contribution
        for (int i = tid; i < BQ * HH; i += 128) po[i] = 0.f;
        if (tid < BQ) { pm[tid] = -CUDART_INF_F; pl[tid] = 0.f; }
        return;
    }

    __shared__ float Qs[64][32];
    __shared__ float Ks[64][64];
    __shared__ float Vs[64][64];
    __shared__ float Ps[32][64];

    // load Q tile (transposed)
    {
        int q  = tid >> 2;
        int hb = (tid & 3) << 4;
        const float4* qr = (const float4*)(g_q + (size_t)(b * TT + qt * BQ + q) * HH + hb);
#pragma unroll
        for (int i = 0; i < 4; ++i) {
            float4 v = qr[i];
            Qs[hb + 4 * i + 0][q] = v.x;
            Qs[hb + 4 * i + 1][q] = v.y;
            Qs[hb + 4 * i + 2][q] = v.z;
            Qs[hb + 4 * i + 3][q] = v.w;
        }
    }

    ull o2[4][2];
    float m[4], l[4];
#pragma unroll
    for (int i = 0; i < 4; ++i) {
        m[i] = -CUDART_INF_F; l[i] = 0.f;
        o2[i][0] = 0ULL; o2[i][1] = 0ULL;
    }

    int k_ld  = tid >> 2;                 // 0..31 (two keys per thread: +0, +32)
    int hb_ld = (tid & 3) << 4;

    for (int kt = t0; kt < t1; ++kt) {
        __syncthreads();
        // K tile (transposed), V tile (natural)
        {
#pragma unroll
            for (int kk = 0; kk < 2; ++kk) {
                int kx = k_ld + kk * 32;
                const float4* kr = (const float4*)(g_k + (size_t)(b * TT + kt * BK + kx) * HH + hb_ld);
#pragma unroll
                for (int i = 0; i < 4; ++i) {
                    float4 v = kr[i];
                    Ks[hb_ld + 4 * i + 0][kx] = v.x;
                    Ks[hb_ld + 4 * i + 1][kx] = v.y;
                    Ks[hb_ld + 4 * i + 2][kx] = v.z;
                    Ks[hb_ld + 4 * i + 3][kx] = v.w;
                }
            }
            const float4* vsrc = (const float4*)(g_v + (size_t)(b * TT + kt * BK) * HH);
            float4* vdst = (float4*)&Vs[0][0];
#pragma unroll
            for (int r = 0; r < 8; ++r)
                vdst[tid + 128 * r] = vsrc[tid + 128 * r];
        }
        __syncthreads();

        // S = Q K^T (packed f32x2)
        ull s2[4][2];
#pragma unroll
        for (int i = 0; i < 4; ++i) { s2[i][0] = 0ULL; s2[i][1] = 0ULL; }

#pragma unroll 8
        for (int h = 0; h < HH; ++h) {
            float4 a = *(const float4*)&Qs[h][ty << 2];
            ulonglong2 bp = *(const ulonglong2*)&Ks[h][tx << 2];
            ull a0 = dup2(a.x), a1 = dup2(a.y), a2 = dup2(a.z), a3 = dup2(a.w);
            ffma2(s2[0][0], a0, bp.x); ffma2(s2[0][1], a0, bp.y);
            ffma2(s2[1][0], a1, bp.x); ffma2(s2[1][1], a1, bp.y);
            ffma2(s2[2][0], a2, bp.x); ffma2(s2[2][1], a2, bp.y);
            ffma2(s2[3][0], a3, bp.x); ffma2(s2[3][1], a3, bp.y);
        }

        float sv[4][4];
#pragma unroll
        for (int i = 0; i < 4; ++i) {
            float2 lo = up2(s2[i][0]);
            float2 hi = up2(s2[i][1]);
            sv[i][0] = lo.x; sv[i][1] = lo.y; sv[i][2] = hi.x; sv[i][3] = hi.y;
        }

        const float scale = 0.125f;
        bool lastkt = (kt == nkt - 1);
#pragma unroll
        for (int i = 0; i < 4; ++i) {
            int qg = qt * BQ + (ty << 2) + i;
#pragma unroll
            for (int j = 0; j < 4; ++j) {
                sv[i][j] *= scale;
                if (lastkt) {
                    int kg = kt * BK + (tx << 2) + j;
                    if (kg > qg) sv[i][j] = -CUDART_INF_F;
                }
            }
        }

        // online softmax per row
#pragma unroll
        for (int i = 0; i < 4; ++i) {
            float rm = fmaxf(fmaxf(sv[i][0], sv[i][1]), fmaxf(sv[i][2], sv[i][3]));
#pragma unroll
            for (int off = 8; off; off >>= 1)
                rm = fmaxf(rm, __shfl_xor_sync(0xffffffff, rm, off));
            float mn = fmaxf(m[i], rm);
            float corr = __expf(m[i] - mn);
            m[i] = mn;
            float rs = 0.f;
#pragma unroll
            for (int j = 0; j < 4; ++j) {
                float p = __expf(sv[i][j] - mn);
                sv[i][j] = p;
                rs += p;
            }
#pragma unroll
            for (int off = 8; off; off >>= 1)
                rs += __shfl_xor_sync(0xffffffff, rs, off);
            l[i] = l[i] * corr + rs;
            ull cd = dup2(corr);
            o2[i][0] = mul2(o2[i][0], cd);
            o2[i][1] = mul2(o2[i][1], cd);
            *(float4*)&Ps[(ty << 2) + i][tx << 2] =
                make_float4(sv[i][0], sv[i][1], sv[i][2], sv[i][3]);
        }
        __syncthreads();

        // O += P V (packed f32x2)
#pragma unroll 4
        for (int k4 = 0; k4 < 16; ++k4) {
            float4 p0 = *(const float4*)&Ps[(ty << 2) + 0][k4 << 2];
            float4 p1 = *(const float4*)&Ps[(ty << 2) + 1][k4 << 2];
            float4 p2 = *(const float4*)&Ps[(ty << 2) + 2][k4 << 2];
            float4 p3 = *(const float4*)&Ps[(ty << 2) + 3][k4 << 2];
#pragma unroll
            for (int r = 0; r < 4; ++r) {
                ulonglong2 vp = *(const ulonglong2*)&Vs[(k4 << 2) + r][tx << 2];
                float pa = (r == 0) ? p0.x : (r == 1) ? p0.y : (r == 2) ? p0.z : p0.w;
                float pb = (r == 0) ? p1.x : (r == 1) ? p1.y : (r == 2) ? p1.z : p1.w;
                float pc = (r == 0) ? p2.x : (r == 1) ? p2.y : (r == 2) ? p2.z : p2.w;
                float pd = (r == 0) ? p3.x : (r == 1) ? p3.y : (r == 2) ? p3.z : p3.w;
                ull da = dup2(pa), db = dup2(pb), dc = dup2(pc), dd = dup2(pd);
                ffma2(o2[0][0], da, vp.x); ffma2(o2[0][1], da, vp.y);
                ffma2(o2[1][0], db, vp.x); ffma2(o2[1][1], db, vp.y);
                ffma2(o2[2][0], dc, vp.x); ffma2(o2[2][1], dc, vp.y);
                ffma2(o2[3][0], dd, vp.x); ffma2(o2[3][1], dd, vp.y);
            }
        }
    }

    // write unnormalized partials
#pragma unroll
    for (int i = 0; i < 4; ++i) {
        int r_loc = (ty << 2) + i;
        float2 lo = up2(o2[i][0]);
        float2 hi = up2(o2[i][1]);
        float4 r = make_float4(lo.x, lo.y, hi.x, hi.y);
        *(float4*)&po[(size_t)r_loc * HH + (tx << 2)] = r;
        if (tx == 0) { pm[r_loc] = m[i]; pl[r_loc] = l[i]; }
    }
}

// ---------------------------------------------------------------------------
// Combine kv-split partials: out = (sum_s w_s * O_s) / (sum_s w_s * l_s)
// ---------------------------------------------------------------------------
__global__ __launch_bounds__(256) void combine_kernel(float* __restrict__ out)
{
    int idx = blockIdx.x * 256 + threadIdx.x;   // < BB*TT*HH
    int row = idx >> 6;                          // b*TT + t

    const int MS = BB * TT;                      // 8192
    const int PS = BB * TT * HH;                 // 524288

    float m0 = g_pm[row], m1 = g_pm[MS + row],
          m2 = g_pm[2 * MS + row], m3 = g_pm[3 * MS + row];
    float ms = fmaxf(fmaxf(m0, m1), fmaxf(m2, m3));
    float w0 = __expf(m0 - ms), w1 = __expf(m1 - ms);
    float w2 = __expf(m2 - ms), w3 = __expf(m3 - ms);
    float lt = w0 * g_pl[row] + w1 * g_pl[MS + row]
             + w2 * g_pl[2 * MS + row] + w3 * g_pl[3 * MS + row];
    float ov = w0 * g_po[idx] + w1 * g_po[PS + idx]
             + w2 * g_po[2 * PS + idx] + w3 * g_po[3 * PS + idx];
    out[idx] = ov / lt;
}

extern "C" void kernel_launch(void* const* d_in, const int* in_sizes, int n_in,
                              void* d_out, int out_size)
{
    const float* x  = (const float*)d_in[0];
    const float* Wq = (const float*)d_in[1];
    const float* Wk = (const float*)d_in[2];
    const float* Wv = (const float*)d_in[3];
    float* out = (float*)d_out;

    qkv_kernel<<<128 * 3, 256>>>(x, Wq, Wk, Wv);
    attn_split_kernel<<<64 * 4 * NS, 128>>>();
    combine_kernel<<<(BB * TT * HH) / 256, 256>>>(out);
}